// round 2
// baseline (speedup 1.0000x reference)
#include <cuda_runtime.h>
#include <cstdint>

#define M_DIM 8192
#define N_DIM 4096
#define K_DIM 4096

// ---------------- scratch (device globals; no runtime allocation) ----------
__device__ float  g_W[(size_t)N_DIM * K_DIM];   // effective weight, tf32-rounded
__device__ float  g_xd[(size_t)M_DIM * K_DIM];  // dropout+ARD scaled x, tf32-rounded
__device__ float  g_ard[K_DIM];                 // softplus(alpha)*softplus(beta)
__device__ float  g_bias[N_DIM];                // effective bias
__device__ double g_wkl;                        // sum of weight KL terms (pre 0.5x)
__device__ double g_klsmall;                    // 0.5*bias_kl_sum + ard_kl_sum

// ---------------- helpers --------------------------------------------------
__device__ __forceinline__ float softplusf(float x) {
    return (x > 20.0f) ? x : log1pf(__expf(x));
}

__device__ __forceinline__ float round_tf32(float x) {
    uint32_t r;
    asm("cvt.rna.tf32.f32 %0, %1;" : "=r"(r) : "f"(x));
    return __uint_as_float(r);
}

__device__ __forceinline__ void cp_async16(void* dst_smem, const void* src) {
    uint32_t d = (uint32_t)__cvta_generic_to_shared(dst_smem);
    asm volatile("cp.async.cg.shared.global [%0], [%1], 16;\n" :: "r"(d), "l"(src));
}
__device__ __forceinline__ void cp_commit() { asm volatile("cp.async.commit_group;\n" ::: "memory"); }
__device__ __forceinline__ void cp_wait_1() { asm volatile("cp.async.wait_group 1;\n" ::: "memory"); }
__device__ __forceinline__ void cp_wait_0() { asm volatile("cp.async.wait_group 0;\n" ::: "memory"); }

// ---------------- small prep: bias', ard_scale, bias+ard KL ----------------
__global__ void small_prep_kernel(const float* __restrict__ bias_mu,
                                  const float* __restrict__ bias_rho,
                                  const float* __restrict__ ard_alpha,
                                  const float* __restrict__ ard_beta,
                                  const float* __restrict__ bias_noise) {
    int tid = threadIdx.x;
    float sb_part = 0.f, sard_part = 0.f;

    for (int i = tid; i < N_DIM; i += 256) {
        float mu  = bias_mu[i];
        float sig = softplusf(bias_rho[i]);
        g_bias[i] = fmaf(sig, bias_noise[i], mu);
        float inv = __fdividef(1.0f, sig);
        sb_part += 2.0f * __logf(sig) + fmaf(inv, inv, fmaf(mu, mu, -1.0f));
    }
    for (int i = tid; i < K_DIM; i += 256) {
        float sa = softplusf(ard_alpha[i]);
        float sb = softplusf(ard_beta[i]);
        g_ard[i] = sa * sb;
        sard_part += sa + sb - __logf(sa) - __logf(sb);
    }

    __shared__ float r1[256], r2[256];
    r1[tid] = sb_part; r2[tid] = sard_part;
    __syncthreads();
    for (int s = 128; s > 0; s >>= 1) {
        if (tid < s) { r1[tid] += r1[tid + s]; r2[tid] += r2[tid + s]; }
        __syncthreads();
    }
    if (tid == 0) {
        g_klsmall = 0.5 * (double)r1[0] + (double)r2[0];
        g_wkl = 0.0;   // zeroed here; weight_prep runs after (stream-ordered)
    }
}

// ---------------- weight prep: W' + weight KL reduce -----------------------
__global__ void weight_prep_kernel(const float4* __restrict__ wmu,
                                   const float4* __restrict__ wrho,
                                   const float4* __restrict__ wnoise) {
    const int n4 = (N_DIM * K_DIM) / 4;
    float4* W4 = reinterpret_cast<float4*>(g_W);
    float part = 0.f;

    int stride = gridDim.x * blockDim.x;
    for (int i = blockIdx.x * blockDim.x + threadIdx.x; i < n4; i += stride) {
        float4 mu = wmu[i], rho = wrho[i], nz = wnoise[i];
        float4 w;
        {
            float sig = softplusf(rho.x);
            w.x = round_tf32(fmaf(sig, nz.x, mu.x));
            float inv = __fdividef(1.0f, sig);
            part += 2.0f * __logf(sig) + fmaf(inv, inv, fmaf(mu.x, mu.x, -1.0f));
        }
        {
            float sig = softplusf(rho.y);
            w.y = round_tf32(fmaf(sig, nz.y, mu.y));
            float inv = __fdividef(1.0f, sig);
            part += 2.0f * __logf(sig) + fmaf(inv, inv, fmaf(mu.y, mu.y, -1.0f));
        }
        {
            float sig = softplusf(rho.z);
            w.z = round_tf32(fmaf(sig, nz.z, mu.z));
            float inv = __fdividef(1.0f, sig);
            part += 2.0f * __logf(sig) + fmaf(inv, inv, fmaf(mu.z, mu.z, -1.0f));
        }
        {
            float sig = softplusf(rho.w);
            w.w = round_tf32(fmaf(sig, nz.w, mu.w));
            float inv = __fdividef(1.0f, sig);
            part += 2.0f * __logf(sig) + fmaf(inv, inv, fmaf(mu.w, mu.w, -1.0f));
        }
        W4[i] = w;
    }

    // warp + block reduce, then one double atomic per block
    for (int off = 16; off; off >>= 1) part += __shfl_xor_sync(0xFFFFFFFFu, part, off);
    __shared__ float wsum[8];
    int lane = threadIdx.x & 31, warp = threadIdx.x >> 5;
    if (lane == 0) wsum[warp] = part;
    __syncthreads();
    if (threadIdx.x == 0) {
        float s = 0.f;
        #pragma unroll
        for (int i = 0; i < 8; i++) s += wsum[i];
        atomicAdd(&g_wkl, (double)s);
    }
}

// ---------------- xd: dropout + ARD scaling --------------------------------
__global__ void xd_kernel(const float4* __restrict__ x,
                          const float4* __restrict__ u) {
    const float keep = 0.9f;
    const float inv_keep = 1.0f / 0.9f;
    const int n4 = (M_DIM * K_DIM) / 4;
    const float4* ard4 = reinterpret_cast<const float4*>(g_ard);
    float4* out4 = reinterpret_cast<float4*>(g_xd);

    int stride = gridDim.x * blockDim.x;
    for (int i = blockIdx.x * blockDim.x + threadIdx.x; i < n4; i += stride) {
        int c4 = i & (K_DIM / 4 - 1);
        float4 xv = x[i], uv = u[i], av = __ldg(&ard4[c4]);
        float4 o;
        o.x = round_tf32((uv.x < keep) ? xv.x * inv_keep * av.x : 0.0f);
        o.y = round_tf32((uv.y < keep) ? xv.y * inv_keep * av.y : 0.0f);
        o.z = round_tf32((uv.z < keep) ? xv.z * inv_keep * av.z : 0.0f);
        o.w = round_tf32((uv.w < keep) ? xv.w * inv_keep * av.w : 0.0f);
        out4[i] = o;
    }
}

// ---------------- GEMM: y = xd @ W'^T + bias' (tf32 mma.sync) --------------
// Tiles: BM=128, BN=128, BK=16. 8 warps (2 M x 4 N), warp tile 64x32.
// smem rows padded to 20 floats -> conflict-free for both cp.async stores
// and fragment loads.
#define BK 16
#define LDS_W 20
#define NT_K (K_DIM / BK)

__device__ __forceinline__ void mma_tf32(float* c, const uint32_t* a, const uint32_t* b) {
    asm volatile(
        "mma.sync.aligned.m16n8k8.row.col.f32.tf32.tf32.f32 "
        "{%0,%1,%2,%3}, {%4,%5,%6,%7}, {%8,%9}, {%0,%1,%2,%3};\n"
        : "+f"(c[0]), "+f"(c[1]), "+f"(c[2]), "+f"(c[3])
        : "r"(a[0]), "r"(a[1]), "r"(a[2]), "r"(a[3]), "r"(b[0]), "r"(b[1]));
}

__global__ void __launch_bounds__(256)
gemm_kernel(float* __restrict__ out) {
    __shared__ float sA[2][128 * LDS_W];
    __shared__ float sB[2][128 * LDS_W];

    const int tid  = threadIdx.x;
    const int lane = tid & 31;
    const int warp = tid >> 5;
    const int wm = warp & 1;    // 0..1 -> 64-row slab
    const int wn = warp >> 1;   // 0..3 -> 32-col slab
    const int g = lane >> 2;    // groupID
    const int t = lane & 3;     // thread in group

    const float* gA = g_xd + (size_t)blockIdx.y * 128 * K_DIM;
    const float* gB = g_W  + (size_t)blockIdx.x * 128 * K_DIM;

    // loader: 256 threads, 4 x 16B each (2 rows of A + 2 rows of B)
    const int lr = tid >> 2;          // 0..63
    const int lc = (tid & 3) << 2;    // 0,4,8,12

    float acc[4][4][4];
    #pragma unroll
    for (int mf = 0; mf < 4; mf++)
        #pragma unroll
        for (int nf = 0; nf < 4; nf++)
            #pragma unroll
            for (int k = 0; k < 4; k++) acc[mf][nf][k] = 0.f;

    // prologue: tile 0 -> buffer 0
    {
        const float* a0 = gA;
        const float* b0 = gB;
        cp_async16(&sA[0][lr * LDS_W + lc],        a0 + (size_t)lr * K_DIM + lc);
        cp_async16(&sA[0][(lr + 64) * LDS_W + lc], a0 + (size_t)(lr + 64) * K_DIM + lc);
        cp_async16(&sB[0][lr * LDS_W + lc],        b0 + (size_t)lr * K_DIM + lc);
        cp_async16(&sB[0][(lr + 64) * LDS_W + lc], b0 + (size_t)(lr + 64) * K_DIM + lc);
        cp_commit();
    }

    for (int kt = 0; kt < NT_K; kt++) {
        const int buf = kt & 1;
        if (kt + 1 < NT_K) {
            const float* a1 = gA + (size_t)(kt + 1) * BK;
            const float* b1 = gB + (size_t)(kt + 1) * BK;
            const int nb = buf ^ 1;
            cp_async16(&sA[nb][lr * LDS_W + lc],        a1 + (size_t)lr * K_DIM + lc);
            cp_async16(&sA[nb][(lr + 64) * LDS_W + lc], a1 + (size_t)(lr + 64) * K_DIM + lc);
            cp_async16(&sB[nb][lr * LDS_W + lc],        b1 + (size_t)lr * K_DIM + lc);
            cp_async16(&sB[nb][(lr + 64) * LDS_W + lc], b1 + (size_t)(lr + 64) * K_DIM + lc);
            cp_commit();
            cp_wait_1();
        } else {
            cp_wait_0();
        }
        __syncthreads();

        const float* As = sA[buf];
        const float* Bs = sB[buf];

        #pragma unroll
        for (int ks = 0; ks < 2; ks++) {
            const int k0 = ks * 8;
            uint32_t a[4][4], b[4][2];
            #pragma unroll
            for (int mf = 0; mf < 4; mf++) {
                const float* p = As + (wm * 64 + mf * 16 + g) * LDS_W + k0 + t;
                a[mf][0] = __float_as_uint(p[0]);
                a[mf][1] = __float_as_uint(p[8 * LDS_W]);
                a[mf][2] = __float_as_uint(p[4]);
                a[mf][3] = __float_as_uint(p[8 * LDS_W + 4]);
            }
            #pragma unroll
            for (int nf = 0; nf < 4; nf++) {
                const float* p = Bs + (wn * 32 + nf * 8 + g) * LDS_W + k0 + t;
                b[nf][0] = __float_as_uint(p[0]);
                b[nf][1] = __float_as_uint(p[4]);
            }
            #pragma unroll
            for (int mf = 0; mf < 4; mf++)
                #pragma unroll
                for (int nf = 0; nf < 4; nf++)
                    mma_tf32(acc[mf][nf], a[mf], b[nf]);
        }
        __syncthreads();
    }

    // epilogue: + bias, float2 stores
    const int rowBase = blockIdx.y * 128 + wm * 64;
    const int colBase = blockIdx.x * 128 + wn * 32;
    #pragma unroll
    for (int mf = 0; mf < 4; mf++) {
        const int r = rowBase + mf * 16 + g;
        #pragma unroll
        for (int nf = 0; nf < 4; nf++) {
            const int c = colBase + nf * 8 + 2 * t;
            float2 bia = *reinterpret_cast<const float2*>(&g_bias[c]);
            float2 v0 = make_float2(acc[mf][nf][0] + bia.x, acc[mf][nf][1] + bia.y);
            float2 v1 = make_float2(acc[mf][nf][2] + bia.x, acc[mf][nf][3] + bia.y);
            *reinterpret_cast<float2*>(&out[(size_t)r * N_DIM + c])       = v0;
            *reinterpret_cast<float2*>(&out[(size_t)(r + 8) * N_DIM + c]) = v1;
        }
    }
}

// ---------------- KL scalar write ------------------------------------------
__global__ void kl_write_kernel(float* __restrict__ out) {
    if (threadIdx.x == 0) {
        out[(size_t)M_DIM * N_DIM] = (float)(0.5 * g_wkl + g_klsmall);
    }
}

// ---------------- launch ----------------------------------------------------
extern "C" void kernel_launch(void* const* d_in, const int* in_sizes, int n_in,
                              void* d_out, int out_size) {
    const float* x    = (const float*)d_in[0];
    const float* wmu  = (const float*)d_in[1];
    const float* wrho = (const float*)d_in[2];
    const float* bmu  = (const float*)d_in[3];
    const float* brho = (const float*)d_in[4];
    const float* aal  = (const float*)d_in[5];
    const float* abe  = (const float*)d_in[6];
    const float* wno  = (const float*)d_in[7];
    const float* bno  = (const float*)d_in[8];
    const float* du   = (const float*)d_in[9];
    float* out = (float*)d_out;

    small_prep_kernel<<<1, 256>>>(bmu, brho, aal, abe, bno);
    weight_prep_kernel<<<2048, 256>>>((const float4*)wmu, (const float4*)wrho,
                                      (const float4*)wno);
    xd_kernel<<<2048, 256>>>((const float4*)x, (const float4*)du);

    dim3 grid(N_DIM / 128, M_DIM / 128);
    gemm_kernel<<<grid, 256>>>(out);

    if ((long long)out_size > (long long)M_DIM * N_DIM) {
        kl_write_kernel<<<1, 32>>>(out);
    }
}

// round 5
// speedup vs baseline: 1.0309x; 1.0309x over previous
#include <cuda_runtime.h>
#include <cstdint>

#define M_DIM 8192
#define N_DIM 4096
#define K_DIM 4096

// ---------------- scratch (device globals; no runtime allocation) ----------
__device__ __align__(1024) float g_W[(size_t)N_DIM * K_DIM];   // effective weight
__device__ __align__(1024) float g_xd[(size_t)M_DIM * K_DIM];  // scaled x
__device__ float  g_ard[K_DIM];
__device__ float  g_bias[N_DIM];
__device__ double g_wkl;
__device__ double g_klsmall;

// ---------------- helpers --------------------------------------------------
__device__ __forceinline__ float softplusf(float x) {
    return (x > 20.0f) ? x : log1pf(__expf(x));
}
__device__ __forceinline__ float round_tf32(float x) {
    uint32_t r;
    asm("cvt.rna.tf32.f32 %0, %1;" : "=r"(r) : "f"(x));
    return __uint_as_float(r);
}
__device__ __forceinline__ void cp_async16(void* dst_smem, const void* src) {
    uint32_t d = (uint32_t)__cvta_generic_to_shared(dst_smem);
    asm volatile("cp.async.cg.shared.global [%0], [%1], 16;\n" :: "r"(d), "l"(src));
}
__device__ __forceinline__ void cp_commit() { asm volatile("cp.async.commit_group;\n" ::: "memory"); }
__device__ __forceinline__ void cp_wait_1() { asm volatile("cp.async.wait_group 1;\n" ::: "memory"); }
__device__ __forceinline__ void cp_wait_0() { asm volatile("cp.async.wait_group 0;\n" ::: "memory"); }

// ---------------- small prep: bias', ard_scale, bias+ard KL ----------------
__global__ void small_prep_kernel(const float* __restrict__ bias_mu,
                                  const float* __restrict__ bias_rho,
                                  const float* __restrict__ ard_alpha,
                                  const float* __restrict__ ard_beta,
                                  const float* __restrict__ bias_noise) {
    int tid = threadIdx.x;
    float sb_part = 0.f, sard_part = 0.f;

    for (int i = tid; i < N_DIM; i += 256) {
        float mu  = bias_mu[i];
        float sig = softplusf(bias_rho[i]);
        g_bias[i] = fmaf(sig, bias_noise[i], mu);
        float inv = __fdividef(1.0f, sig);
        sb_part += 2.0f * __logf(sig) + fmaf(inv, inv, fmaf(mu, mu, -1.0f));
    }
    for (int i = tid; i < K_DIM; i += 256) {
        float sa = softplusf(ard_alpha[i]);
        float sb = softplusf(ard_beta[i]);
        g_ard[i] = sa * sb;
        sard_part += sa + sb - __logf(sa) - __logf(sb);
    }

    __shared__ float r1[256], r2[256];
    r1[tid] = sb_part; r2[tid] = sard_part;
    __syncthreads();
    for (int s = 128; s > 0; s >>= 1) {
        if (tid < s) { r1[tid] += r1[tid + s]; r2[tid] += r2[tid + s]; }
        __syncthreads();
    }
    if (tid == 0) {
        g_klsmall = 0.5 * (double)r1[0] + (double)r2[0];
        g_wkl = 0.0;
    }
}

// ---------------- weight prep: W' + weight KL reduce -----------------------
__global__ void weight_prep_kernel(const float4* __restrict__ wmu,
                                   const float4* __restrict__ wrho,
                                   const float4* __restrict__ wnoise) {
    const int n4 = (N_DIM * K_DIM) / 4;
    float4* W4 = reinterpret_cast<float4*>(g_W);
    float part = 0.f;

    int stride = gridDim.x * blockDim.x;
    for (int i = blockIdx.x * blockDim.x + threadIdx.x; i < n4; i += stride) {
        float4 mu = wmu[i], rho = wrho[i], nz = wnoise[i];
        float4 w;
        {
            float sig = softplusf(rho.x);
            w.x = round_tf32(fmaf(sig, nz.x, mu.x));
            float inv = __fdividef(1.0f, sig);
            part += 2.0f * __logf(sig) + fmaf(inv, inv, fmaf(mu.x, mu.x, -1.0f));
        }
        {
            float sig = softplusf(rho.y);
            w.y = round_tf32(fmaf(sig, nz.y, mu.y));
            float inv = __fdividef(1.0f, sig);
            part += 2.0f * __logf(sig) + fmaf(inv, inv, fmaf(mu.y, mu.y, -1.0f));
        }
        {
            float sig = softplusf(rho.z);
            w.z = round_tf32(fmaf(sig, nz.z, mu.z));
            float inv = __fdividef(1.0f, sig);
            part += 2.0f * __logf(sig) + fmaf(inv, inv, fmaf(mu.z, mu.z, -1.0f));
        }
        {
            float sig = softplusf(rho.w);
            w.w = round_tf32(fmaf(sig, nz.w, mu.w));
            float inv = __fdividef(1.0f, sig);
            part += 2.0f * __logf(sig) + fmaf(inv, inv, fmaf(mu.w, mu.w, -1.0f));
        }
        W4[i] = w;
    }

    for (int off = 16; off; off >>= 1) part += __shfl_xor_sync(0xFFFFFFFFu, part, off);
    __shared__ float wsum[8];
    int lane = threadIdx.x & 31, warp = threadIdx.x >> 5;
    if (lane == 0) wsum[warp] = part;
    __syncthreads();
    if (threadIdx.x == 0) {
        float s = 0.f;
        #pragma unroll
        for (int i = 0; i < 8; i++) s += wsum[i];
        atomicAdd(&g_wkl, (double)s);
    }
}

// ---------------- xd: dropout + ARD scaling --------------------------------
__global__ void xd_kernel(const float4* __restrict__ x,
                          const float4* __restrict__ u) {
    const float keep = 0.9f;
    const float inv_keep = 1.0f / 0.9f;
    const int n4 = (M_DIM * K_DIM) / 4;
    const float4* ard4 = reinterpret_cast<const float4*>(g_ard);
    float4* out4 = reinterpret_cast<float4*>(g_xd);

    int stride = gridDim.x * blockDim.x;
    for (int i = blockIdx.x * blockDim.x + threadIdx.x; i < n4; i += stride) {
        int c4 = i & (K_DIM / 4 - 1);
        float4 xv = x[i], uv = u[i], av = __ldg(&ard4[c4]);
        float4 o;
        o.x = round_tf32((uv.x < keep) ? xv.x * inv_keep * av.x : 0.0f);
        o.y = round_tf32((uv.y < keep) ? xv.y * inv_keep * av.y : 0.0f);
        o.z = round_tf32((uv.z < keep) ? xv.z * inv_keep * av.z : 0.0f);
        o.w = round_tf32((uv.w < keep) ? xv.w * inv_keep * av.w : 0.0f);
        out4[i] = o;
    }
}

// ---------------- GEMM: y = xd @ W'^T + bias' (tf32 mma.sync) --------------
// CTA tile 128x256, BK=16. 8 warps in 2(M) x 4(N); warp tile 64x64
// (4 x 8 fragments of m16n8k8). 3-stage cp.async pipeline, one
// __syncthreads per K-iteration. smem rows padded to 20 floats.
#define BK 16
#define LDS_W 20
#define NT_K (K_DIM / BK)          // 256
#define A_FLOATS (128 * LDS_W)     // 2560
#define B_FLOATS (256 * LDS_W)     // 5120
#define STG_FLOATS (A_FLOATS + B_FLOATS)           // 7680
#define GSMEM_BYTES (3 * STG_FLOATS * 4)           // 92160

__device__ __forceinline__ void mma_tf32(float* c, const uint32_t* a, const uint32_t* b) {
    asm volatile(
        "mma.sync.aligned.m16n8k8.row.col.f32.tf32.tf32.f32 "
        "{%0,%1,%2,%3}, {%4,%5,%6,%7}, {%8,%9}, {%0,%1,%2,%3};\n"
        : "+f"(c[0]), "+f"(c[1]), "+f"(c[2]), "+f"(c[3])
        : "r"(a[0]), "r"(a[1]), "r"(a[2]), "r"(a[3]), "r"(b[0]), "r"(b[1]));
}

// loader: 256 threads fill one stage (A: 512 x 16B ops, B: 1024 x 16B ops)
__device__ __forceinline__ void load_stage(float* sm, const float* gA, const float* gB,
                                           int tid) {
    float* sA = sm;
    float* sB = sm + A_FLOATS;
    #pragma unroll
    for (int j = 0; j < 2; j++) {
        int o = tid + 256 * j;
        int row = o >> 2, c = (o & 3) << 2;
        cp_async16(&sA[row * LDS_W + c], gA + (size_t)row * K_DIM + c);
    }
    #pragma unroll
    for (int j = 0; j < 4; j++) {
        int o = tid + 256 * j;
        int row = o >> 2, c = (o & 3) << 2;
        cp_async16(&sB[row * LDS_W + c], gB + (size_t)row * K_DIM + c);
    }
    cp_commit();
}

__global__ void __launch_bounds__(256, 1)
gemm_kernel(float* __restrict__ out) {
    extern __shared__ float smem[];

    const int tid  = threadIdx.x;
    const int lane = tid & 31;
    const int warp = tid >> 5;
    const int wm = warp & 1;    // 0..1 -> 64-row slab
    const int wn = warp >> 1;   // 0..3 -> 64-col slab
    const int g = lane >> 2;
    const int t = lane & 3;

    const float* gA = g_xd + (size_t)blockIdx.y * 128 * K_DIM;
    const float* gB = g_W  + (size_t)blockIdx.x * 256 * K_DIM;

    float acc[4][8][4];
    #pragma unroll
    for (int mf = 0; mf < 4; mf++)
        #pragma unroll
        for (int nf = 0; nf < 8; nf++)
            #pragma unroll
            for (int k = 0; k < 4; k++) acc[mf][nf][k] = 0.f;

    // prologue: stages 0 and 1
    load_stage(smem,              gA,      gB,      tid);
    load_stage(smem + STG_FLOATS, gA + BK, gB + BK, tid);

    int buf = 0;
    for (int kt = 0; kt < NT_K; kt++) {
        if (kt < NT_K - 1) cp_wait_1(); else cp_wait_0();
        __syncthreads();

        // issue stage kt+2 into the buffer freed at kt-1 (all warps are past
        // the barrier, so compute on that buffer is complete everywhere)
        if (kt + 2 < NT_K) {
            int nb = buf + 2; if (nb >= 3) nb -= 3;
            load_stage(smem + nb * STG_FLOATS,
                       gA + (size_t)(kt + 2) * BK, gB + (size_t)(kt + 2) * BK, tid);
        }

        const float* As = smem + buf * STG_FLOATS;
        const float* Bs = As + A_FLOATS;

        #pragma unroll
        for (int ks = 0; ks < 2; ks++) {
            const int k0 = ks * 8;
            uint32_t a[4][4], b[8][2];
            #pragma unroll
            for (int mf = 0; mf < 4; mf++) {
                const float* p = As + (wm * 64 + mf * 16 + g) * LDS_W + k0 + t;
                a[mf][0] = __float_as_uint(p[0]);
                a[mf][1] = __float_as_uint(p[8 * LDS_W]);
                a[mf][2] = __float_as_uint(p[4]);
                a[mf][3] = __float_as_uint(p[8 * LDS_W + 4]);
            }
            #pragma unroll
            for (int nf = 0; nf < 8; nf++) {
                const float* p = Bs + (wn * 64 + nf * 8 + g) * LDS_W + k0 + t;
                b[nf][0] = __float_as_uint(p[0]);
                b[nf][1] = __float_as_uint(p[4]);
            }
            #pragma unroll
            for (int mf = 0; mf < 4; mf++)
                #pragma unroll
                for (int nf = 0; nf < 8; nf++)
                    mma_tf32(acc[mf][nf], a[mf], b[nf]);
        }

        if (++buf == 3) buf = 0;
    }

    // epilogue: + bias, float2 stores
    const int rowBase = blockIdx.y * 128 + wm * 64;
    const int colBase = blockIdx.x * 256 + wn * 64;
    #pragma unroll
    for (int mf = 0; mf < 4; mf++) {
        const int r = rowBase + mf * 16 + g;
        #pragma unroll
        for (int nf = 0; nf < 8; nf++) {
            const int c = colBase + nf * 8 + 2 * t;
            float2 bia = *reinterpret_cast<const float2*>(&g_bias[c]);
            float2 v0 = make_float2(acc[mf][nf][0] + bia.x, acc[mf][nf][1] + bia.y);
            float2 v1 = make_float2(acc[mf][nf][2] + bia.x, acc[mf][nf][3] + bia.y);
            *reinterpret_cast<float2*>(&out[(size_t)r * N_DIM + c])       = v0;
            *reinterpret_cast<float2*>(&out[(size_t)(r + 8) * N_DIM + c]) = v1;
        }
    }
}

// ---------------- KL scalar write ------------------------------------------
__global__ void kl_write_kernel(float* __restrict__ out) {
    if (threadIdx.x == 0) {
        out[(size_t)M_DIM * N_DIM] = (float)(0.5 * g_wkl + g_klsmall);
    }
}

// ---------------- launch ----------------------------------------------------
extern "C" void kernel_launch(void* const* d_in, const int* in_sizes, int n_in,
                              void* d_out, int out_size) {
    const float* x    = (const float*)d_in[0];
    const float* wmu  = (const float*)d_in[1];
    const float* wrho = (const float*)d_in[2];
    const float* bmu  = (const float*)d_in[3];
    const float* brho = (const float*)d_in[4];
    const float* aal  = (const float*)d_in[5];
    const float* abe  = (const float*)d_in[6];
    const float* wno  = (const float*)d_in[7];
    const float* bno  = (const float*)d_in[8];
    const float* du   = (const float*)d_in[9];
    float* out = (float*)d_out;

    static bool attr_done = false;
    if (!attr_done) {
        cudaFuncSetAttribute(gemm_kernel,
                             cudaFuncAttributeMaxDynamicSharedMemorySize,
                             GSMEM_BYTES);
        attr_done = true;
    }

    small_prep_kernel<<<1, 256>>>(bmu, brho, aal, abe, bno);
    weight_prep_kernel<<<2048, 256>>>((const float4*)wmu, (const float4*)wrho,
                                      (const float4*)wno);
    xd_kernel<<<2048, 256>>>((const float4*)x, (const float4*)du);

    dim3 grid(N_DIM / 256, M_DIM / 128);   // (16, 64)
    gemm_kernel<<<grid, 256, GSMEM_BYTES>>>(out);

    if ((long long)out_size > (long long)M_DIM * N_DIM) {
        kl_write_kernel<<<1, 32>>>(out);
    }
}

// round 6
// speedup vs baseline: 1.9355x; 1.8775x over previous
#include <cuda_runtime.h>
#include <cuda_fp16.h>
#include <cstdint>

#define M_DIM 8192
#define N_DIM 4096
#define K_DIM 4096

// ---------------- scratch (device globals; no runtime allocation) ----------
__device__ __align__(1024) __half g_W[(size_t)N_DIM * K_DIM];   // effective weight (fp16)
__device__ __align__(1024) __half g_xd[(size_t)M_DIM * K_DIM];  // scaled x (fp16)
__device__ float  g_ard[K_DIM];
__device__ float  g_bias[N_DIM];
__device__ double g_wkl;
__device__ double g_klsmall;

// ---------------- helpers --------------------------------------------------
__device__ __forceinline__ float softplusf(float x) {
    return (x > 20.0f) ? x : log1pf(__expf(x));
}
__device__ __forceinline__ void cp_async16(void* dst_smem, const void* src) {
    uint32_t d = (uint32_t)__cvta_generic_to_shared(dst_smem);
    asm volatile("cp.async.cg.shared.global [%0], [%1], 16;\n" :: "r"(d), "l"(src));
}
__device__ __forceinline__ void cp_commit() { asm volatile("cp.async.commit_group;\n" ::: "memory"); }
__device__ __forceinline__ void cp_wait_1() { asm volatile("cp.async.wait_group 1;\n" ::: "memory"); }
__device__ __forceinline__ void cp_wait_0() { asm volatile("cp.async.wait_group 0;\n" ::: "memory"); }

// ---------------- small prep: bias', ard_scale, bias+ard KL ----------------
__global__ void small_prep_kernel(const float* __restrict__ bias_mu,
                                  const float* __restrict__ bias_rho,
                                  const float* __restrict__ ard_alpha,
                                  const float* __restrict__ ard_beta,
                                  const float* __restrict__ bias_noise) {
    int tid = threadIdx.x;
    float sb_part = 0.f, sard_part = 0.f;

    for (int i = tid; i < N_DIM; i += 256) {
        float mu  = bias_mu[i];
        float sig = softplusf(bias_rho[i]);
        g_bias[i] = fmaf(sig, bias_noise[i], mu);
        float inv = __fdividef(1.0f, sig);
        sb_part += 2.0f * __logf(sig) + fmaf(inv, inv, fmaf(mu, mu, -1.0f));
    }
    for (int i = tid; i < K_DIM; i += 256) {
        float sa = softplusf(ard_alpha[i]);
        float sb = softplusf(ard_beta[i]);
        g_ard[i] = sa * sb;
        sard_part += sa + sb - __logf(sa) - __logf(sb);
    }

    __shared__ float r1[256], r2[256];
    r1[tid] = sb_part; r2[tid] = sard_part;
    __syncthreads();
    for (int s = 128; s > 0; s >>= 1) {
        if (tid < s) { r1[tid] += r1[tid + s]; r2[tid] += r2[tid + s]; }
        __syncthreads();
    }
    if (tid == 0) {
        g_klsmall = 0.5 * (double)r1[0] + (double)r2[0];
        g_wkl = 0.0;
    }
}

// ---------------- weight prep: W'(fp16) + weight KL reduce -----------------
__global__ void weight_prep_kernel(const float4* __restrict__ wmu,
                                   const float4* __restrict__ wrho,
                                   const float4* __restrict__ wnoise) {
    const int n4 = (N_DIM * K_DIM) / 4;
    __half2* W2 = reinterpret_cast<__half2*>(g_W);
    float part = 0.f;

    int stride = gridDim.x * blockDim.x;
    for (int i = blockIdx.x * blockDim.x + threadIdx.x; i < n4; i += stride) {
        float4 mu = wmu[i], rho = wrho[i], nz = wnoise[i];
        float wx, wy, wz, ww;
        {
            float sig = softplusf(rho.x);
            wx = fmaf(sig, nz.x, mu.x);
            float inv = __fdividef(1.0f, sig);
            part += 2.0f * __logf(sig) + fmaf(inv, inv, fmaf(mu.x, mu.x, -1.0f));
        }
        {
            float sig = softplusf(rho.y);
            wy = fmaf(sig, nz.y, mu.y);
            float inv = __fdividef(1.0f, sig);
            part += 2.0f * __logf(sig) + fmaf(inv, inv, fmaf(mu.y, mu.y, -1.0f));
        }
        {
            float sig = softplusf(rho.z);
            wz = fmaf(sig, nz.z, mu.z);
            float inv = __fdividef(1.0f, sig);
            part += 2.0f * __logf(sig) + fmaf(inv, inv, fmaf(mu.z, mu.z, -1.0f));
        }
        {
            float sig = softplusf(rho.w);
            ww = fmaf(sig, nz.w, mu.w);
            float inv = __fdividef(1.0f, sig);
            part += 2.0f * __logf(sig) + fmaf(inv, inv, fmaf(mu.w, mu.w, -1.0f));
        }
        W2[2 * i]     = __floats2half2_rn(wx, wy);
        W2[2 * i + 1] = __floats2half2_rn(wz, ww);
    }

    for (int off = 16; off; off >>= 1) part += __shfl_xor_sync(0xFFFFFFFFu, part, off);
    __shared__ float wsum[8];
    int lane = threadIdx.x & 31, warp = threadIdx.x >> 5;
    if (lane == 0) wsum[warp] = part;
    __syncthreads();
    if (threadIdx.x == 0) {
        float s = 0.f;
        #pragma unroll
        for (int i = 0; i < 8; i++) s += wsum[i];
        atomicAdd(&g_wkl, (double)s);
    }
}

// ---------------- xd: dropout + ARD scaling (fp16 out) ---------------------
__global__ void xd_kernel(const float4* __restrict__ x,
                          const float4* __restrict__ u) {
    const float keep = 0.9f;
    const float inv_keep = 1.0f / 0.9f;
    const int n4 = (M_DIM * K_DIM) / 4;
    const float4* ard4 = reinterpret_cast<const float4*>(g_ard);
    __half2* out2 = reinterpret_cast<__half2*>(g_xd);

    int stride = gridDim.x * blockDim.x;
    for (int i = blockIdx.x * blockDim.x + threadIdx.x; i < n4; i += stride) {
        int c4 = i & (K_DIM / 4 - 1);
        float4 xv = x[i], uv = u[i], av = __ldg(&ard4[c4]);
        float ox = (uv.x < keep) ? xv.x * inv_keep * av.x : 0.0f;
        float oy = (uv.y < keep) ? xv.y * inv_keep * av.y : 0.0f;
        float oz = (uv.z < keep) ? xv.z * inv_keep * av.z : 0.0f;
        float ow = (uv.w < keep) ? xv.w * inv_keep * av.w : 0.0f;
        out2[2 * i]     = __floats2half2_rn(ox, oy);
        out2[2 * i + 1] = __floats2half2_rn(oz, ow);
    }
}

// ---------------- GEMM: y = xd @ W'^T + bias' (fp16 mma.sync) --------------
// CTA tile 128x256, BK=32 halves. 8 warps in 2(M) x 4(N); warp tile 64x64
// (4 x 8 fragments of m16n8k16). 3-stage cp.async pipeline, one
// __syncthreads per K-iteration. smem rows = 40 halves (conflict-free).
#define BK 32
#define LDS_WH 40                      // halves per smem row
#define NT_K (K_DIM / BK)              // 128
#define A_HALVES (128 * LDS_WH)        // 5120
#define B_HALVES (256 * LDS_WH)        // 10240
#define STG_HALVES (A_HALVES + B_HALVES)           // 15360
#define GSMEM_BYTES (3 * STG_HALVES * 2)           // 92160

__device__ __forceinline__ void mma_f16(float* c, const uint32_t* a, const uint32_t* b) {
    asm volatile(
        "mma.sync.aligned.m16n8k16.row.col.f32.f16.f16.f32 "
        "{%0,%1,%2,%3}, {%4,%5,%6,%7}, {%8,%9}, {%0,%1,%2,%3};\n"
        : "+f"(c[0]), "+f"(c[1]), "+f"(c[2]), "+f"(c[3])
        : "r"(a[0]), "r"(a[1]), "r"(a[2]), "r"(a[3]), "r"(b[0]), "r"(b[1]));
}

// loader: 256 threads fill one stage. Rows hold 32 halves = 4 x 16B chunks.
__device__ __forceinline__ void load_stage(__half* sm, const __half* gA, const __half* gB,
                                           int tid) {
    __half* sA = sm;
    __half* sB = sm + A_HALVES;
    #pragma unroll
    for (int j = 0; j < 2; j++) {           // A: 128 rows x 4 chunks = 512 ops
        int o = tid + 256 * j;
        int row = o >> 2, c = (o & 3) << 3; // chunk of 8 halves
        cp_async16(&sA[row * LDS_WH + c], gA + (size_t)row * K_DIM + c);
    }
    #pragma unroll
    for (int j = 0; j < 4; j++) {           // B: 256 rows x 4 chunks = 1024 ops
        int o = tid + 256 * j;
        int row = o >> 2, c = (o & 3) << 3;
        cp_async16(&sB[row * LDS_WH + c], gB + (size_t)row * K_DIM + c);
    }
    cp_commit();
}

__global__ void __launch_bounds__(256, 1)
gemm_kernel(float* __restrict__ out) {
    extern __shared__ __half smem[];

    const int tid  = threadIdx.x;
    const int lane = tid & 31;
    const int warp = tid >> 5;
    const int wm = warp & 1;    // 0..1 -> 64-row slab
    const int wn = warp >> 1;   // 0..3 -> 64-col slab
    const int g = lane >> 2;
    const int t = lane & 3;

    const __half* gA = g_xd + (size_t)blockIdx.y * 128 * K_DIM;
    const __half* gB = g_W  + (size_t)blockIdx.x * 256 * K_DIM;

    float acc[4][8][4];
    #pragma unroll
    for (int mf = 0; mf < 4; mf++)
        #pragma unroll
        for (int nf = 0; nf < 8; nf++)
            #pragma unroll
            for (int k = 0; k < 4; k++) acc[mf][nf][k] = 0.f;

    // prologue: stages 0 and 1
    load_stage(smem,              gA,      gB,      tid);
    load_stage(smem + STG_HALVES, gA + BK, gB + BK, tid);

    int buf = 0;
    for (int kt = 0; kt < NT_K; kt++) {
        if (kt < NT_K - 1) cp_wait_1(); else cp_wait_0();
        __syncthreads();

        if (kt + 2 < NT_K) {
            int nb = buf + 2; if (nb >= 3) nb -= 3;
            load_stage(smem + nb * STG_HALVES,
                       gA + (size_t)(kt + 2) * BK, gB + (size_t)(kt + 2) * BK, tid);
        }

        const __half* As = smem + buf * STG_HALVES;
        const __half* Bs = As + A_HALVES;

        #pragma unroll
        for (int ks = 0; ks < 2; ks++) {
            const int k0 = ks * 16;
            uint32_t a[4][4], b[8][2];
            #pragma unroll
            for (int mf = 0; mf < 4; mf++) {
                const uint32_t* p = reinterpret_cast<const uint32_t*>(
                    As + (wm * 64 + mf * 16 + g) * LDS_WH + k0 + 2 * t);
                a[mf][0] = p[0];
                a[mf][1] = p[(8 * LDS_WH) / 2];
                a[mf][2] = p[4];
                a[mf][3] = p[(8 * LDS_WH) / 2 + 4];
            }
            #pragma unroll
            for (int nf = 0; nf < 8; nf++) {
                const uint32_t* p = reinterpret_cast<const uint32_t*>(
                    Bs + (wn * 64 + nf * 8 + g) * LDS_WH + k0 + 2 * t);
                b[nf][0] = p[0];
                b[nf][1] = p[4];
            }
            #pragma unroll
            for (int mf = 0; mf < 4; mf++)
                #pragma unroll
                for (int nf = 0; nf < 8; nf++)
                    mma_f16(acc[mf][nf], a[mf], b[nf]);
        }

        if (++buf == 3) buf = 0;
    }

    // epilogue: + bias, float2 stores
    const int rowBase = blockIdx.y * 128 + wm * 64;
    const int colBase = blockIdx.x * 256 + wn * 64;
    #pragma unroll
    for (int mf = 0; mf < 4; mf++) {
        const int r = rowBase + mf * 16 + g;
        #pragma unroll
        for (int nf = 0; nf < 8; nf++) {
            const int c = colBase + nf * 8 + 2 * t;
            float2 bia = *reinterpret_cast<const float2*>(&g_bias[c]);
            float2 v0 = make_float2(acc[mf][nf][0] + bia.x, acc[mf][nf][1] + bia.y);
            float2 v1 = make_float2(acc[mf][nf][2] + bia.x, acc[mf][nf][3] + bia.y);
            *reinterpret_cast<float2*>(&out[(size_t)r * N_DIM + c])       = v0;
            *reinterpret_cast<float2*>(&out[(size_t)(r + 8) * N_DIM + c]) = v1;
        }
    }
}

// ---------------- KL scalar write ------------------------------------------
__global__ void kl_write_kernel(float* __restrict__ out) {
    if (threadIdx.x == 0) {
        out[(size_t)M_DIM * N_DIM] = (float)(0.5 * g_wkl + g_klsmall);
    }
}

// ---------------- launch ----------------------------------------------------
extern "C" void kernel_launch(void* const* d_in, const int* in_sizes, int n_in,
                              void* d_out, int out_size) {
    const float* x    = (const float*)d_in[0];
    const float* wmu  = (const float*)d_in[1];
    const float* wrho = (const float*)d_in[2];
    const float* bmu  = (const float*)d_in[3];
    const float* brho = (const float*)d_in[4];
    const float* aal  = (const float*)d_in[5];
    const float* abe  = (const float*)d_in[6];
    const float* wno  = (const float*)d_in[7];
    const float* bno  = (const float*)d_in[8];
    const float* du   = (const float*)d_in[9];
    float* out = (float*)d_out;

    static bool attr_done = false;
    if (!attr_done) {
        cudaFuncSetAttribute(gemm_kernel,
                             cudaFuncAttributeMaxDynamicSharedMemorySize,
                             GSMEM_BYTES);
        attr_done = true;
    }

    small_prep_kernel<<<1, 256>>>(bmu, brho, aal, abe, bno);
    weight_prep_kernel<<<2048, 256>>>((const float4*)wmu, (const float4*)wrho,
                                      (const float4*)wno);
    xd_kernel<<<2048, 256>>>((const float4*)x, (const float4*)du);

    dim3 grid(N_DIM / 256, M_DIM / 128);   // (16, 64)
    gemm_kernel<<<grid, 256, GSMEM_BYTES>>>(out);

    if ((long long)out_size > (long long)M_DIM * N_DIM) {
        kl_write_kernel<<<1, 32>>>(out);
    }
}

// round 7
// speedup vs baseline: 1.9610x; 1.0132x over previous
#include <cuda_runtime.h>
#include <cuda_fp16.h>
#include <cstdint>

#define M_DIM 8192
#define N_DIM 4096
#define K_DIM 4096

// ---------------- scratch (device globals; no runtime allocation) ----------
__device__ __align__(1024) __half g_W[(size_t)N_DIM * K_DIM];   // effective weight (fp16)
__device__ __align__(1024) __half g_xd[(size_t)M_DIM * K_DIM];  // scaled x (fp16)
__device__ float  g_ard[K_DIM];
__device__ float  g_bias[N_DIM];
__device__ double g_wkl;
__device__ double g_klsmall;

// ---------------- helpers --------------------------------------------------
__device__ __forceinline__ float softplusf(float x) {
    return (x > 20.0f) ? x : log1pf(__expf(x));
}
__device__ __forceinline__ void cp_async16(void* dst_smem, const void* src) {
    uint32_t d = (uint32_t)__cvta_generic_to_shared(dst_smem);
    asm volatile("cp.async.cg.shared.global [%0], [%1], 16;\n" :: "r"(d), "l"(src));
}
__device__ __forceinline__ void cp_commit() { asm volatile("cp.async.commit_group;\n" ::: "memory"); }
__device__ __forceinline__ void cp_wait_1() { asm volatile("cp.async.wait_group 1;\n" ::: "memory"); }
__device__ __forceinline__ void cp_wait_0() { asm volatile("cp.async.wait_group 0;\n" ::: "memory"); }

__device__ __forceinline__ void ldsm_x4(uint32_t* d, uint32_t saddr) {
    asm volatile("ldmatrix.sync.aligned.m8n8.x4.shared.b16 {%0,%1,%2,%3}, [%4];"
                 : "=r"(d[0]), "=r"(d[1]), "=r"(d[2]), "=r"(d[3]) : "r"(saddr));
}

// ---------------- small prep: bias', ard_scale, bias+ard KL ----------------
__global__ void small_prep_kernel(const float* __restrict__ bias_mu,
                                  const float* __restrict__ bias_rho,
                                  const float* __restrict__ ard_alpha,
                                  const float* __restrict__ ard_beta,
                                  const float* __restrict__ bias_noise) {
    int tid = threadIdx.x;
    float sb_part = 0.f, sard_part = 0.f;

    for (int i = tid; i < N_DIM; i += 256) {
        float mu  = bias_mu[i];
        float sig = softplusf(bias_rho[i]);
        g_bias[i] = fmaf(sig, bias_noise[i], mu);
        float inv = __fdividef(1.0f, sig);
        sb_part += 2.0f * __logf(sig) + fmaf(inv, inv, fmaf(mu, mu, -1.0f));
    }
    for (int i = tid; i < K_DIM; i += 256) {
        float sa = softplusf(ard_alpha[i]);
        float sb = softplusf(ard_beta[i]);
        g_ard[i] = sa * sb;
        sard_part += sa + sb - __logf(sa) - __logf(sb);
    }

    __shared__ float r1[256], r2[256];
    r1[tid] = sb_part; r2[tid] = sard_part;
    __syncthreads();
    for (int s = 128; s > 0; s >>= 1) {
        if (tid < s) { r1[tid] += r1[tid + s]; r2[tid] += r2[tid + s]; }
        __syncthreads();
    }
    if (tid == 0) {
        g_klsmall = 0.5 * (double)r1[0] + (double)r2[0];
        g_wkl = 0.0;
    }
}

// ---------------- weight prep: W'(fp16) + weight KL reduce -----------------
__global__ void weight_prep_kernel(const float4* __restrict__ wmu,
                                   const float4* __restrict__ wrho,
                                   const float4* __restrict__ wnoise) {
    const int n4 = (N_DIM * K_DIM) / 4;
    __half2* W2 = reinterpret_cast<__half2*>(g_W);
    float part = 0.f;

    int stride = gridDim.x * blockDim.x;
    for (int i = blockIdx.x * blockDim.x + threadIdx.x; i < n4; i += stride) {
        float4 mu = wmu[i], rho = wrho[i], nz = wnoise[i];
        float wx, wy, wz, ww;
        {
            float sig = softplusf(rho.x);
            wx = fmaf(sig, nz.x, mu.x);
            float inv = __fdividef(1.0f, sig);
            part += 2.0f * __logf(sig) + fmaf(inv, inv, fmaf(mu.x, mu.x, -1.0f));
        }
        {
            float sig = softplusf(rho.y);
            wy = fmaf(sig, nz.y, mu.y);
            float inv = __fdividef(1.0f, sig);
            part += 2.0f * __logf(sig) + fmaf(inv, inv, fmaf(mu.y, mu.y, -1.0f));
        }
        {
            float sig = softplusf(rho.z);
            wz = fmaf(sig, nz.z, mu.z);
            float inv = __fdividef(1.0f, sig);
            part += 2.0f * __logf(sig) + fmaf(inv, inv, fmaf(mu.z, mu.z, -1.0f));
        }
        {
            float sig = softplusf(rho.w);
            ww = fmaf(sig, nz.w, mu.w);
            float inv = __fdividef(1.0f, sig);
            part += 2.0f * __logf(sig) + fmaf(inv, inv, fmaf(mu.w, mu.w, -1.0f));
        }
        W2[2 * i]     = __floats2half2_rn(wx, wy);
        W2[2 * i + 1] = __floats2half2_rn(wz, ww);
    }

    for (int off = 16; off; off >>= 1) part += __shfl_xor_sync(0xFFFFFFFFu, part, off);
    __shared__ float wsum[8];
    int lane = threadIdx.x & 31, warp = threadIdx.x >> 5;
    if (lane == 0) wsum[warp] = part;
    __syncthreads();
    if (threadIdx.x == 0) {
        float s = 0.f;
        #pragma unroll
        for (int i = 0; i < 8; i++) s += wsum[i];
        atomicAdd(&g_wkl, (double)s);
    }
}

// ---------------- xd: dropout + ARD scaling (fp16 out) ---------------------
__global__ void xd_kernel(const float4* __restrict__ x,
                          const float4* __restrict__ u) {
    const float keep = 0.9f;
    const float inv_keep = 1.0f / 0.9f;
    const int n4 = (M_DIM * K_DIM) / 4;
    const float4* ard4 = reinterpret_cast<const float4*>(g_ard);
    __half2* out2 = reinterpret_cast<__half2*>(g_xd);

    int stride = gridDim.x * blockDim.x;
    for (int i = blockIdx.x * blockDim.x + threadIdx.x; i < n4; i += stride) {
        int c4 = i & (K_DIM / 4 - 1);
        float4 xv = x[i], uv = u[i], av = __ldg(&ard4[c4]);
        float ox = (uv.x < keep) ? xv.x * inv_keep * av.x : 0.0f;
        float oy = (uv.y < keep) ? xv.y * inv_keep * av.y : 0.0f;
        float oz = (uv.z < keep) ? xv.z * inv_keep * av.z : 0.0f;
        float ow = (uv.w < keep) ? xv.w * inv_keep * av.w : 0.0f;
        out2[2 * i]     = __floats2half2_rn(ox, oy);
        out2[2 * i + 1] = __floats2half2_rn(oz, ow);
    }
}

// ---------------- GEMM: y = xd @ W'^T + bias' (fp16 mma.sync) --------------
// CTA tile 128x256, BK=32 halves. 8 warps in 2(M) x 4(N); warp tile 64x64
// (4 x 8 fragments of m16n8k16). 3-stage cp.async pipeline, one
// __syncthreads per K-iteration. Fragments via ldmatrix.x4.
// smem rows = 40 halves (80B stride -> conflict-free LDSM phases).
#define BK 32
#define LDS_WH 40
#define NT_K (K_DIM / BK)              // 128
#define A_HALVES (128 * LDS_WH)        // 5120
#define B_HALVES (256 * LDS_WH)        // 10240
#define STG_HALVES (A_HALVES + B_HALVES)           // 15360
#define GSMEM_BYTES (3 * STG_HALVES * 2)           // 92160

__device__ __forceinline__ void mma_f16(float* c, const uint32_t* a, const uint32_t* b) {
    asm volatile(
        "mma.sync.aligned.m16n8k16.row.col.f32.f16.f16.f32 "
        "{%0,%1,%2,%3}, {%4,%5,%6,%7}, {%8,%9}, {%0,%1,%2,%3};\n"
        : "+f"(c[0]), "+f"(c[1]), "+f"(c[2]), "+f"(c[3])
        : "r"(a[0]), "r"(a[1]), "r"(a[2]), "r"(a[3]), "r"(b[0]), "r"(b[1]));
}

__device__ __forceinline__ void load_stage(__half* sm, const __half* gA, const __half* gB,
                                           int tid) {
    __half* sA = sm;
    __half* sB = sm + A_HALVES;
    #pragma unroll
    for (int j = 0; j < 2; j++) {
        int o = tid + 256 * j;
        int row = o >> 2, c = (o & 3) << 3;
        cp_async16(&sA[row * LDS_WH + c], gA + (size_t)row * K_DIM + c);
    }
    #pragma unroll
    for (int j = 0; j < 4; j++) {
        int o = tid + 256 * j;
        int row = o >> 2, c = (o & 3) << 3;
        cp_async16(&sB[row * LDS_WH + c], gB + (size_t)row * K_DIM + c);
    }
    cp_commit();
}

__global__ void __launch_bounds__(256, 1)
gemm_kernel(float* __restrict__ out) {
    extern __shared__ __half smem[];

    const int tid  = threadIdx.x;
    const int lane = tid & 31;
    const int warp = tid >> 5;
    const int wm = warp & 1;
    const int wn = warp >> 1;
    const int g = lane >> 2;
    const int t = lane & 3;

    const __half* gA = g_xd + (size_t)blockIdx.y * 128 * K_DIM;
    const __half* gB = g_W  + (size_t)blockIdx.x * 256 * K_DIM;

    // ldmatrix per-thread addressing (in halves, relative to tile starts)
    const int rA = lane & 15;              // row within 16-row A fragment
    const int cA = (lane >> 4) << 3;       // 0 or 8 (k-half select)
    const int qB = lane >> 3;              // 0..3 quadrant for B x4
    const int rB = lane & 7;
    const int bRowSel = (qB & 2) << 2;     // 0 or 8 (second n-fragment)
    const int bColSel = (qB & 1) << 3;     // 0 or 8 (k-half)

    float acc[4][8][4];
    #pragma unroll
    for (int mf = 0; mf < 4; mf++)
        #pragma unroll
        for (int nf = 0; nf < 8; nf++)
            #pragma unroll
            for (int k = 0; k < 4; k++) acc[mf][nf][k] = 0.f;

    load_stage(smem,              gA,      gB,      tid);
    load_stage(smem + STG_HALVES, gA + BK, gB + BK, tid);

    int buf = 0;
    for (int kt = 0; kt < NT_K; kt++) {
        if (kt < NT_K - 1) cp_wait_1(); else cp_wait_0();
        __syncthreads();

        if (kt + 2 < NT_K) {
            int nb = buf + 2; if (nb >= 3) nb -= 3;
            load_stage(smem + nb * STG_HALVES,
                       gA + (size_t)(kt + 2) * BK, gB + (size_t)(kt + 2) * BK, tid);
        }

        const __half* As = smem + buf * STG_HALVES;
        const __half* Bs = As + A_HALVES;

        #pragma unroll
        for (int ks = 0; ks < 2; ks++) {
            const int k0 = ks * 16;
            uint32_t a[4][4], b[8][2];
            #pragma unroll
            for (int mf = 0; mf < 4; mf++) {
                uint32_t ad = (uint32_t)__cvta_generic_to_shared(
                    As + (wm * 64 + mf * 16 + rA) * LDS_WH + k0 + cA);
                ldsm_x4(a[mf], ad);
            }
            #pragma unroll
            for (int nf = 0; nf < 8; nf += 2) {
                uint32_t bd = (uint32_t)__cvta_generic_to_shared(
                    Bs + (wn * 64 + nf * 8 + bRowSel + rB) * LDS_WH + k0 + bColSel);
                uint32_t r[4];
                ldsm_x4(r, bd);
                b[nf][0]     = r[0];
                b[nf][1]     = r[1];
                b[nf + 1][0] = r[2];
                b[nf + 1][1] = r[3];
            }
            #pragma unroll
            for (int mf = 0; mf < 4; mf++)
                #pragma unroll
                for (int nf = 0; nf < 8; nf++)
                    mma_f16(acc[mf][nf], a[mf], b[nf]);
        }

        if (++buf == 3) buf = 0;
    }

    // epilogue: + bias, float2 stores
    const int rowBase = blockIdx.y * 128 + wm * 64;
    const int colBase = blockIdx.x * 256 + wn * 64;
    #pragma unroll
    for (int mf = 0; mf < 4; mf++) {
        const int r = rowBase + mf * 16 + g;
        #pragma unroll
        for (int nf = 0; nf < 8; nf++) {
            const int c = colBase + nf * 8 + 2 * t;
            float2 bia = *reinterpret_cast<const float2*>(&g_bias[c]);
            float2 v0 = make_float2(acc[mf][nf][0] + bia.x, acc[mf][nf][1] + bia.y);
            float2 v1 = make_float2(acc[mf][nf][2] + bia.x, acc[mf][nf][3] + bia.y);
            *reinterpret_cast<float2*>(&out[(size_t)r * N_DIM + c])       = v0;
            *reinterpret_cast<float2*>(&out[(size_t)(r + 8) * N_DIM + c]) = v1;
        }
    }
}

// ---------------- KL scalar write ------------------------------------------
__global__ void kl_write_kernel(float* __restrict__ out) {
    if (threadIdx.x == 0) {
        out[(size_t)M_DIM * N_DIM] = (float)(0.5 * g_wkl + g_klsmall);
    }
}

// ---------------- launch ----------------------------------------------------
extern "C" void kernel_launch(void* const* d_in, const int* in_sizes, int n_in,
                              void* d_out, int out_size) {
    const float* x    = (const float*)d_in[0];
    const float* wmu  = (const float*)d_in[1];
    const float* wrho = (const float*)d_in[2];
    const float* bmu  = (const float*)d_in[3];
    const float* brho = (const float*)d_in[4];
    const float* aal  = (const float*)d_in[5];
    const float* abe  = (const float*)d_in[6];
    const float* wno  = (const float*)d_in[7];
    const float* bno  = (const float*)d_in[8];
    const float* du   = (const float*)d_in[9];
    float* out = (float*)d_out;

    static bool attr_done = false;
    if (!attr_done) {
        cudaFuncSetAttribute(gemm_kernel,
                             cudaFuncAttributeMaxDynamicSharedMemorySize,
                             GSMEM_BYTES);
        attr_done = true;
    }

    small_prep_kernel<<<1, 256>>>(bmu, brho, aal, abe, bno);
    weight_prep_kernel<<<2048, 256>>>((const float4*)wmu, (const float4*)wrho,
                                      (const float4*)wno);
    xd_kernel<<<2048, 256>>>((const float4*)x, (const float4*)du);

    dim3 grid(N_DIM / 256, M_DIM / 128);   // (16, 64)
    gemm_kernel<<<grid, 256, GSMEM_BYTES>>>(out);

    if ((long long)out_size > (long long)M_DIM * N_DIM) {
        kl_write_kernel<<<1, 32>>>(out);
    }
}

// round 8
// speedup vs baseline: 1.9671x; 1.0031x over previous
#include <cuda_runtime.h>
#include <cuda_fp16.h>
#include <cstdint>

#define M_DIM 8192
#define N_DIM 4096
#define K_DIM 4096

// ---------------- scratch (device globals; no runtime allocation) ----------
__device__ __align__(1024) __half g_W[(size_t)N_DIM * K_DIM];   // effective weight (fp16)
__device__ __align__(1024) __half g_xd[(size_t)M_DIM * K_DIM];  // scaled x (fp16)
__device__ float  g_ard[K_DIM];
__device__ float  g_bias[N_DIM];
__device__ double g_wkl;
__device__ double g_klsmall;

// ---------------- helpers --------------------------------------------------
__device__ __forceinline__ float softplusf(float x) {
    return (x > 20.0f) ? x : log1pf(__expf(x));
}
__device__ __forceinline__ void cp_async16(void* dst_smem, const void* src) {
    uint32_t d = (uint32_t)__cvta_generic_to_shared(dst_smem);
    asm volatile("cp.async.cg.shared.global [%0], [%1], 16;\n" :: "r"(d), "l"(src));
}
__device__ __forceinline__ void cp_commit() { asm volatile("cp.async.commit_group;\n" ::: "memory"); }
__device__ __forceinline__ void cp_wait_1() { asm volatile("cp.async.wait_group 1;\n" ::: "memory"); }
__device__ __forceinline__ void cp_wait_0() { asm volatile("cp.async.wait_group 0;\n" ::: "memory"); }

__device__ __forceinline__ void ldsm_x4(uint32_t* d, uint32_t saddr) {
    asm volatile("ldmatrix.sync.aligned.m8n8.x4.shared.b16 {%0,%1,%2,%3}, [%4];"
                 : "=r"(d[0]), "=r"(d[1]), "=r"(d[2]), "=r"(d[3]) : "r"(saddr));
}

// ---------------- small prep: bias', ard_scale, bias+ard KL ----------------
__global__ void small_prep_kernel(const float* __restrict__ bias_mu,
                                  const float* __restrict__ bias_rho,
                                  const float* __restrict__ ard_alpha,
                                  const float* __restrict__ ard_beta,
                                  const float* __restrict__ bias_noise) {
    int tid = threadIdx.x;
    float sb_part = 0.f, sard_part = 0.f;

    for (int i = tid; i < N_DIM; i += 256) {
        float mu  = bias_mu[i];
        float sig = softplusf(bias_rho[i]);
        g_bias[i] = fmaf(sig, bias_noise[i], mu);
        float inv = __fdividef(1.0f, sig);
        sb_part += 2.0f * __logf(sig) + fmaf(inv, inv, fmaf(mu, mu, -1.0f));
    }
    for (int i = tid; i < K_DIM; i += 256) {
        float sa = softplusf(ard_alpha[i]);
        float sb = softplusf(ard_beta[i]);
        g_ard[i] = sa * sb;
        sard_part += sa + sb - __logf(sa) - __logf(sb);
    }

    __shared__ float r1[256], r2[256];
    r1[tid] = sb_part; r2[tid] = sard_part;
    __syncthreads();
    for (int s = 128; s > 0; s >>= 1) {
        if (tid < s) { r1[tid] += r1[tid + s]; r2[tid] += r2[tid + s]; }
        __syncthreads();
    }
    if (tid == 0) {
        g_klsmall = 0.5 * (double)r1[0] + (double)r2[0];
        g_wkl = 0.0;
    }
}

// ---------------- weight prep: W'(fp16) + weight KL reduce -----------------
__global__ void weight_prep_kernel(const float4* __restrict__ wmu,
                                   const float4* __restrict__ wrho,
                                   const float4* __restrict__ wnoise) {
    const int n4 = (N_DIM * K_DIM) / 4;
    __half2* W2 = reinterpret_cast<__half2*>(g_W);
    float part = 0.f;

    int stride = gridDim.x * blockDim.x;
    for (int i = blockIdx.x * blockDim.x + threadIdx.x; i < n4; i += stride) {
        float4 mu = wmu[i], rho = wrho[i], nz = wnoise[i];
        float wx, wy, wz, ww;
        {
            float sig = softplusf(rho.x);
            wx = fmaf(sig, nz.x, mu.x);
            float inv = __fdividef(1.0f, sig);
            part += 2.0f * __logf(sig) + fmaf(inv, inv, fmaf(mu.x, mu.x, -1.0f));
        }
        {
            float sig = softplusf(rho.y);
            wy = fmaf(sig, nz.y, mu.y);
            float inv = __fdividef(1.0f, sig);
            part += 2.0f * __logf(sig) + fmaf(inv, inv, fmaf(mu.y, mu.y, -1.0f));
        }
        {
            float sig = softplusf(rho.z);
            wz = fmaf(sig, nz.z, mu.z);
            float inv = __fdividef(1.0f, sig);
            part += 2.0f * __logf(sig) + fmaf(inv, inv, fmaf(mu.z, mu.z, -1.0f));
        }
        {
            float sig = softplusf(rho.w);
            ww = fmaf(sig, nz.w, mu.w);
            float inv = __fdividef(1.0f, sig);
            part += 2.0f * __logf(sig) + fmaf(inv, inv, fmaf(mu.w, mu.w, -1.0f));
        }
        W2[2 * i]     = __floats2half2_rn(wx, wy);
        W2[2 * i + 1] = __floats2half2_rn(wz, ww);
    }

    for (int off = 16; off; off >>= 1) part += __shfl_xor_sync(0xFFFFFFFFu, part, off);
    __shared__ float wsum[8];
    int lane = threadIdx.x & 31, warp = threadIdx.x >> 5;
    if (lane == 0) wsum[warp] = part;
    __syncthreads();
    if (threadIdx.x == 0) {
        float s = 0.f;
        #pragma unroll
        for (int i = 0; i < 8; i++) s += wsum[i];
        atomicAdd(&g_wkl, (double)s);
    }
}

// ---------------- xd: dropout + ARD scaling (fp16 out) ---------------------
__global__ void xd_kernel(const float4* __restrict__ x,
                          const float4* __restrict__ u) {
    const float keep = 0.9f;
    const float inv_keep = 1.0f / 0.9f;
    const int n4 = (M_DIM * K_DIM) / 4;
    const float4* ard4 = reinterpret_cast<const float4*>(g_ard);
    __half2* out2 = reinterpret_cast<__half2*>(g_xd);

    int stride = gridDim.x * blockDim.x;
    for (int i = blockIdx.x * blockDim.x + threadIdx.x; i < n4; i += stride) {
        int c4 = i & (K_DIM / 4 - 1);
        float4 xv = x[i], uv = u[i], av = __ldg(&ard4[c4]);
        float ox = (uv.x < keep) ? xv.x * inv_keep * av.x : 0.0f;
        float oy = (uv.y < keep) ? xv.y * inv_keep * av.y : 0.0f;
        float oz = (uv.z < keep) ? xv.z * inv_keep * av.z : 0.0f;
        float ow = (uv.w < keep) ? xv.w * inv_keep * av.w : 0.0f;
        out2[2 * i]     = __floats2half2_rn(ox, oy);
        out2[2 * i + 1] = __floats2half2_rn(oz, ow);
    }
}

// ---------------- GEMM: y = xd @ W'^T + bias' (fp16 mma.sync) --------------
// CTA tile 128x256, BK=32. 8 warps (2Mx4N), warp tile 64x64. 3-stage
// cp.async pipeline. Per K-tile: load ALL fragments (both k-halves,
// 32 LDSM -> 64 regs) first, then run all 64 MMAs as one uninterrupted
// tensor burst. smem rows = 40 halves (conflict-free LDSM phases).
#define BK 32
#define LDS_WH 40
#define NT_K (K_DIM / BK)              // 128
#define A_HALVES (128 * LDS_WH)        // 5120
#define B_HALVES (256 * LDS_WH)        // 10240
#define STG_HALVES (A_HALVES + B_HALVES)           // 15360
#define GSMEM_BYTES (3 * STG_HALVES * 2)           // 92160

__device__ __forceinline__ void mma_f16(float* c, const uint32_t* a, const uint32_t* b) {
    asm volatile(
        "mma.sync.aligned.m16n8k16.row.col.f32.f16.f16.f32 "
        "{%0,%1,%2,%3}, {%4,%5,%6,%7}, {%8,%9}, {%0,%1,%2,%3};\n"
        : "+f"(c[0]), "+f"(c[1]), "+f"(c[2]), "+f"(c[3])
        : "r"(a[0]), "r"(a[1]), "r"(a[2]), "r"(a[3]), "r"(b[0]), "r"(b[1]));
}

__device__ __forceinline__ void load_stage(__half* sm, const __half* gA, const __half* gB,
                                           int tid) {
    __half* sA = sm;
    __half* sB = sm + A_HALVES;
    #pragma unroll
    for (int j = 0; j < 2; j++) {
        int o = tid + 256 * j;
        int row = o >> 2, c = (o & 3) << 3;
        cp_async16(&sA[row * LDS_WH + c], gA + (size_t)row * K_DIM + c);
    }
    #pragma unroll
    for (int j = 0; j < 4; j++) {
        int o = tid + 256 * j;
        int row = o >> 2, c = (o & 3) << 3;
        cp_async16(&sB[row * LDS_WH + c], gB + (size_t)row * K_DIM + c);
    }
    cp_commit();
}

__global__ void __launch_bounds__(256, 1)
gemm_kernel(float* __restrict__ out) {
    extern __shared__ __half smem[];

    const int tid  = threadIdx.x;
    const int lane = tid & 31;
    const int warp = tid >> 5;
    const int wm = warp & 1;
    const int wn = warp >> 1;
    const int g = lane >> 2;
    const int t = lane & 3;

    const __half* gA = g_xd + (size_t)blockIdx.y * 128 * K_DIM;
    const __half* gB = g_W  + (size_t)blockIdx.x * 256 * K_DIM;

    const int rA = lane & 15;
    const int cA = (lane >> 4) << 3;
    const int qB = lane >> 3;
    const int rB = lane & 7;
    const int bRowSel = (qB & 2) << 2;
    const int bColSel = (qB & 1) << 3;

    float acc[4][8][4];
    #pragma unroll
    for (int mf = 0; mf < 4; mf++)
        #pragma unroll
        for (int nf = 0; nf < 8; nf++)
            #pragma unroll
            for (int k = 0; k < 4; k++) acc[mf][nf][k] = 0.f;

    load_stage(smem,              gA,      gB,      tid);
    load_stage(smem + STG_HALVES, gA + BK, gB + BK, tid);

    int buf = 0;
    for (int kt = 0; kt < NT_K; kt++) {
        if (kt < NT_K - 1) cp_wait_1(); else cp_wait_0();
        __syncthreads();

        if (kt + 2 < NT_K) {
            int nb = buf + 2; if (nb >= 3) nb -= 3;
            load_stage(smem + nb * STG_HALVES,
                       gA + (size_t)(kt + 2) * BK, gB + (size_t)(kt + 2) * BK, tid);
        }

        const __half* As = smem + buf * STG_HALVES;
        const __half* Bs = As + A_HALVES;

        // ---- phase 1: load ALL fragments for both k-halves ------------------
        uint32_t a[2][4][4], b[2][8][2];
        #pragma unroll
        for (int ks = 0; ks < 2; ks++) {
            const int k0 = ks * 16;
            #pragma unroll
            for (int mf = 0; mf < 4; mf++) {
                uint32_t ad = (uint32_t)__cvta_generic_to_shared(
                    As + (wm * 64 + mf * 16 + rA) * LDS_WH + k0 + cA);
                ldsm_x4(a[ks][mf], ad);
            }
            #pragma unroll
            for (int nf = 0; nf < 8; nf += 2) {
                uint32_t bd = (uint32_t)__cvta_generic_to_shared(
                    Bs + (wn * 64 + nf * 8 + bRowSel + rB) * LDS_WH + k0 + bColSel);
                uint32_t r[4];
                ldsm_x4(r, bd);
                b[ks][nf][0]     = r[0];
                b[ks][nf][1]     = r[1];
                b[ks][nf + 1][0] = r[2];
                b[ks][nf + 1][1] = r[3];
            }
        }

        // ---- phase 2: one uninterrupted 64-MMA tensor burst -----------------
        #pragma unroll
        for (int ks = 0; ks < 2; ks++)
            #pragma unroll
            for (int mf = 0; mf < 4; mf++)
                #pragma unroll
                for (int nf = 0; nf < 8; nf++)
                    mma_f16(acc[mf][nf], a[ks][mf], b[ks][nf]);

        if (++buf == 3) buf = 0;
    }

    // epilogue: + bias, float2 stores
    const int rowBase = blockIdx.y * 128 + wm * 64;
    const int colBase = blockIdx.x * 256 + wn * 64;
    #pragma unroll
    for (int mf = 0; mf < 4; mf++) {
        const int r = rowBase + mf * 16 + g;
        #pragma unroll
        for (int nf = 0; nf < 8; nf++) {
            const int c = colBase + nf * 8 + 2 * t;
            float2 bia = *reinterpret_cast<const float2*>(&g_bias[c]);
            float2 v0 = make_float2(acc[mf][nf][0] + bia.x, acc[mf][nf][1] + bia.y);
            float2 v1 = make_float2(acc[mf][nf][2] + bia.x, acc[mf][nf][3] + bia.y);
            *reinterpret_cast<float2*>(&out[(size_t)r * N_DIM + c])       = v0;
            *reinterpret_cast<float2*>(&out[(size_t)(r + 8) * N_DIM + c]) = v1;
        }
    }
}

// ---------------- KL scalar write ------------------------------------------
__global__ void kl_write_kernel(float* __restrict__ out) {
    if (threadIdx.x == 0) {
        out[(size_t)M_DIM * N_DIM] = (float)(0.5 * g_wkl + g_klsmall);
    }
}

// ---------------- launch ----------------------------------------------------
extern "C" void kernel_launch(void* const* d_in, const int* in_sizes, int n_in,
                              void* d_out, int out_size) {
    const float* x    = (const float*)d_in[0];
    const float* wmu  = (const float*)d_in[1];
    const float* wrho = (const float*)d_in[2];
    const float* bmu  = (const float*)d_in[3];
    const float* brho = (const float*)d_in[4];
    const float* aal  = (const float*)d_in[5];
    const float* abe  = (const float*)d_in[6];
    const float* wno  = (const float*)d_in[7];
    const float* bno  = (const float*)d_in[8];
    const float* du   = (const float*)d_in[9];
    float* out = (float*)d_out;

    static bool attr_done = false;
    if (!attr_done) {
        cudaFuncSetAttribute(gemm_kernel,
                             cudaFuncAttributeMaxDynamicSharedMemorySize,
                             GSMEM_BYTES);
        attr_done = true;
    }

    small_prep_kernel<<<1, 256>>>(bmu, brho, aal, abe, bno);
    weight_prep_kernel<<<2048, 256>>>((const float4*)wmu, (const float4*)wrho,
                                      (const float4*)wno);
    xd_kernel<<<2048, 256>>>((const float4*)x, (const float4*)du);

    dim3 grid(N_DIM / 256, M_DIM / 128);   // (16, 64)
    gemm_kernel<<<grid, 256, GSMEM_BYTES>>>(out);

    if ((long long)out_size > (long long)M_DIM * N_DIM) {
        kl_write_kernel<<<1, 32>>>(out);
    }
}